// round 1
// baseline (speedup 1.0000x reference)
#include <cuda_runtime.h>
#include <cuda_bf16.h>
#include <math.h>

// Problem constants
#define BB 4
#define TT 2048
#define CC 1024
#define HH 16
#define HD 64
#define M_ROWS (BB * TT)       // 8192
#define N3 (3 * CC)            // 3072

// Scratch (device globals -- allocation API is forbidden)
__device__ float g_qkv[(size_t)M_ROWS * N3];     // 100.7 MB
__device__ float g_attn[(size_t)M_ROWS * CC];    // 33.6 MB

// ---------------------------------------------------------------------------
// SGEMM: C[M,N] = A[M,K] @ B[K,N], all row-major, M%128==0, N%128==0, K%16==0
// BM=BN=128, BK=16, 256 threads, 8x8 per thread.
// ---------------------------------------------------------------------------
__global__ __launch_bounds__(256)
void sgemm128(const float* __restrict__ A, const float* __restrict__ B,
              float* __restrict__ C, int M, int N, int K)
{
    __shared__ float As[16][128];   // transposed: As[k][m]
    __shared__ float Bs[16][128];

    const int tid = threadIdx.x;
    const int tx = tid & 15;        // 0..15 -> N direction
    const int ty = tid >> 4;        // 0..15 -> M direction
    const int blockM = blockIdx.y * 128;
    const int blockN = blockIdx.x * 128;

    float acc[8][8];
    #pragma unroll
    for (int i = 0; i < 8; i++)
        #pragma unroll
        for (int j = 0; j < 8; j++) acc[i][j] = 0.0f;

    for (int kb = 0; kb < K; kb += 16) {
        // Load A tile (128 x 16) -> As transposed. 512 float4 total, 2/thread.
        #pragma unroll
        for (int r = 0; r < 2; r++) {
            int li = tid + r * 256;
            int arow = li >> 2;          // 0..127
            int ac4  = (li & 3) * 4;     // 0,4,8,12
            float4 a = *(const float4*)(A + (size_t)(blockM + arow) * K + kb + ac4);
            As[ac4 + 0][arow] = a.x;
            As[ac4 + 1][arow] = a.y;
            As[ac4 + 2][arow] = a.z;
            As[ac4 + 3][arow] = a.w;
        }
        // Load B tile (16 x 128). 512 float4 total, 2/thread.
        #pragma unroll
        for (int r = 0; r < 2; r++) {
            int li = tid + r * 256;
            int brow = li >> 5;          // 0..15
            int bc4  = (li & 31) * 4;    // 0..124
            float4 b = *(const float4*)(B + (size_t)(kb + brow) * N + blockN + bc4);
            *(float4*)&Bs[brow][bc4] = b;
        }
        __syncthreads();

        #pragma unroll
        for (int k = 0; k < 16; k++) {
            float ra[8], rb[8];
            #pragma unroll
            for (int i = 0; i < 8; i++) ra[i] = As[k][ty * 8 + i];
            #pragma unroll
            for (int j = 0; j < 8; j++) rb[j] = Bs[k][tx * 8 + j];
            #pragma unroll
            for (int i = 0; i < 8; i++)
                #pragma unroll
                for (int j = 0; j < 8; j++)
                    acc[i][j] = fmaf(ra[i], rb[j], acc[i][j]);
        }
        __syncthreads();
    }

    // Epilogue
    #pragma unroll
    for (int i = 0; i < 8; i++) {
        float* crow = C + (size_t)(blockM + ty * 8 + i) * N + blockN + tx * 8;
        float4 v0 = make_float4(acc[i][0], acc[i][1], acc[i][2], acc[i][3]);
        float4 v1 = make_float4(acc[i][4], acc[i][5], acc[i][6], acc[i][7]);
        *(float4*)(crow + 0) = v0;
        *(float4*)(crow + 4) = v1;
    }
}

// ---------------------------------------------------------------------------
// Flash attention (causal, fp32). One query row per thread, 128 rows per CTA.
// K/V tiles of 64 keys in shared memory. Online softmax in chunks of 16 keys.
// grid: (T/128, B*H), block: 128 threads.
// ---------------------------------------------------------------------------
__global__ __launch_bounds__(128)
void attn_kernel()
{
    __shared__ float Ks[64][64];
    __shared__ float Vs[64][64];

    const int qt = blockIdx.x;
    const int bh = blockIdx.y;
    const int b  = bh >> 4;          // / H
    const int h  = bh & 15;          // % H

    const float* base = g_qkv + (size_t)b * TT * N3;
    const int q_idx = qt * 128 + threadIdx.x;

    float qreg[HD];
    {
        const float* qp = base + (size_t)q_idx * N3 + h * HD;   // q section
        #pragma unroll
        for (int d4 = 0; d4 < 16; d4++) {
            float4 v = *(const float4*)(qp + d4 * 4);
            qreg[4*d4+0] = v.x * 0.125f;   // 1/sqrt(64)
            qreg[4*d4+1] = v.y * 0.125f;
            qreg[4*d4+2] = v.z * 0.125f;
            qreg[4*d4+3] = v.w * 0.125f;
        }
    }

    float m = -INFINITY, l = 0.0f;
    float acc[HD];
    #pragma unroll
    for (int d = 0; d < HD; d++) acc[d] = 0.0f;

    const int kt_max = 2 * qt + 1;   // last key tile touching this q block

    for (int kt = 0; kt <= kt_max; kt++) {
        // Cooperative load of K and V tiles (64 x 64 each)
        const float* kbase = base + (size_t)kt * 64 * N3 + CC  + h * HD;  // k section
        const float* vbase = base + (size_t)kt * 64 * N3 + 2*CC + h * HD; // v section
        #pragma unroll
        for (int i = 0; i < 8; i++) {
            int idx = threadIdx.x + i * 128;   // 0..1023 float4 slots
            int r = idx >> 4;
            int c = (idx & 15) * 4;
            *(float4*)&Ks[r][c] = *(const float4*)(kbase + (size_t)r * N3 + c);
            *(float4*)&Vs[r][c] = *(const float4*)(vbase + (size_t)r * N3 + c);
        }
        __syncthreads();

        if (q_idx >= kt * 64) {
            const int jlim = q_idx - kt * 64;     // keys with local j > jlim are masked
            #pragma unroll 1
            for (int chunk = 0; chunk < 4; chunk++) {
                float s[16];
                #pragma unroll
                for (int jj = 0; jj < 16; jj++) {
                    int j = chunk * 16 + jj;
                    const float4* kr = (const float4*)Ks[j];
                    float s0 = 0.f, s1 = 0.f, s2 = 0.f, s3 = 0.f;
                    #pragma unroll
                    for (int d4 = 0; d4 < 16; d4 += 4) {
                        float4 k0 = kr[d4+0], k1 = kr[d4+1], k2 = kr[d4+2], k3 = kr[d4+3];
                        s0 = fmaf(qreg[4*(d4+0)+0], k0.x, s0); s0 = fmaf(qreg[4*(d4+0)+1], k0.y, s0);
                        s0 = fmaf(qreg[4*(d4+0)+2], k0.z, s0); s0 = fmaf(qreg[4*(d4+0)+3], k0.w, s0);
                        s1 = fmaf(qreg[4*(d4+1)+0], k1.x, s1); s1 = fmaf(qreg[4*(d4+1)+1], k1.y, s1);
                        s1 = fmaf(qreg[4*(d4+1)+2], k1.z, s1); s1 = fmaf(qreg[4*(d4+1)+3], k1.w, s1);
                        s2 = fmaf(qreg[4*(d4+2)+0], k2.x, s2); s2 = fmaf(qreg[4*(d4+2)+1], k2.y, s2);
                        s2 = fmaf(qreg[4*(d4+2)+2], k2.z, s2); s2 = fmaf(qreg[4*(d4+2)+3], k2.w, s2);
                        s3 = fmaf(qreg[4*(d4+3)+0], k3.x, s3); s3 = fmaf(qreg[4*(d4+3)+1], k3.y, s3);
                        s3 = fmaf(qreg[4*(d4+3)+2], k3.z, s3); s3 = fmaf(qreg[4*(d4+3)+3], k3.w, s3);
                    }
                    float sv = (s0 + s1) + (s2 + s3);
                    s[jj] = (j <= jlim) ? sv : -INFINITY;
                }
                // chunk max
                float cmax = s[0];
                #pragma unroll
                for (int jj = 1; jj < 16; jj++) cmax = fmaxf(cmax, s[jj]);
                if (cmax > m) {
                    float corr = __expf(m - cmax);
                    l *= corr;
                    #pragma unroll
                    for (int d = 0; d < HD; d++) acc[d] *= corr;
                    m = cmax;
                }
                // accumulate P @ V
                #pragma unroll
                for (int jj = 0; jj < 16; jj++) {
                    float p = __expf(s[jj] - m);
                    l += p;
                    const float4* vr = (const float4*)Vs[chunk * 16 + jj];
                    #pragma unroll
                    for (int d4 = 0; d4 < 16; d4++) {
                        float4 vv = vr[d4];
                        acc[4*d4+0] = fmaf(p, vv.x, acc[4*d4+0]);
                        acc[4*d4+1] = fmaf(p, vv.y, acc[4*d4+1]);
                        acc[4*d4+2] = fmaf(p, vv.z, acc[4*d4+2]);
                        acc[4*d4+3] = fmaf(p, vv.w, acc[4*d4+3]);
                    }
                }
            }
        }
        __syncthreads();
    }

    // Write normalized output in [B,T,C] layout (heads merged back)
    const float inv = 1.0f / l;
    float* op = g_attn + (size_t)(b * TT + q_idx) * CC + h * HD;
    #pragma unroll
    for (int d4 = 0; d4 < 16; d4++) {
        float4 v = make_float4(acc[4*d4+0]*inv, acc[4*d4+1]*inv,
                               acc[4*d4+2]*inv, acc[4*d4+3]*inv);
        *(float4*)(op + d4 * 4) = v;
    }
}

// ---------------------------------------------------------------------------
// Launch
// ---------------------------------------------------------------------------
extern "C" void kernel_launch(void* const* d_in, const int* in_sizes, int n_in,
                              void* d_out, int out_size)
{
    const float* x     = (const float*)d_in[0];   // [B,T,C]
    const float* w_qkv = (const float*)d_in[1];   // [C,3C]
    const float* w_out = (const float*)d_in[2];   // [C,C]
    float* out = (float*)d_out;                   // [B,T,C]

    float* qkv_ptr = nullptr;
    float* attn_ptr = nullptr;
    cudaGetSymbolAddress((void**)&qkv_ptr, g_qkv);
    cudaGetSymbolAddress((void**)&attn_ptr, g_attn);

    // 1) QKV projection: [8192,1024] @ [1024,3072]
    {
        dim3 grid(N3 / 128, M_ROWS / 128);
        sgemm128<<<grid, 256>>>(x, w_qkv, qkv_ptr, M_ROWS, N3, CC);
    }
    // 2) Flash attention
    {
        dim3 grid(TT / 128, BB * HH);
        attn_kernel<<<grid, 128>>>();
    }
    // 3) Output projection: [8192,1024] @ [1024,1024]
    {
        dim3 grid(CC / 128, M_ROWS / 128);
        sgemm128<<<grid, 256>>>(attn_ptr, w_out, out, M_ROWS, CC, CC);
    }
}

// round 2
// speedup vs baseline: 4.1580x; 4.1580x over previous
#include <cuda_runtime.h>
#include <math.h>

// Problem constants
#define BB 4
#define TT 2048
#define CC 1024
#define HH 16
#define HD 64
#define M_ROWS (BB * TT)       // 8192
#define N3 (3 * CC)            // 3072

// Scratch (device globals -- allocation API is forbidden)
__device__ float g_qkv[(size_t)M_ROWS * N3];     // 100.7 MB
__device__ float g_attn[(size_t)M_ROWS * CC];    // 33.6 MB

// ---------------------------------------------------------------------------
// Helpers
// ---------------------------------------------------------------------------
__device__ __forceinline__ unsigned f2tf32(float x) {
    unsigned r;
    asm("cvt.rna.tf32.f32 %0, %1;" : "=r"(r) : "f"(x));
    return r;
}
__device__ __forceinline__ float ex2f(float x) {
    float r;
    asm("ex2.approx.ftz.f32 %0, %1;" : "=f"(r) : "f"(x));
    return r;
}
__device__ __forceinline__ void mma_tf32(float* d, const unsigned* a, const unsigned* b) {
    asm volatile(
        "mma.sync.aligned.m16n8k8.row.col.f32.tf32.tf32.f32 "
        "{%0,%1,%2,%3}, {%4,%5,%6,%7}, {%8,%9}, {%0,%1,%2,%3};"
        : "+f"(d[0]), "+f"(d[1]), "+f"(d[2]), "+f"(d[3])
        : "r"(a[0]), "r"(a[1]), "r"(a[2]), "r"(a[3]), "r"(b[0]), "r"(b[1]));
}

// ---------------------------------------------------------------------------
// tf32 tensor GEMM: C[M,N] = A[M,K] @ B[K,N], row-major. M%128==0, N%128==0,
// K%32==0. 256 threads, 8 warps arranged 2(M)x4(N); warp tile 64x32.
// ---------------------------------------------------------------------------
#define GAS 36    // As stride (pad 4) -> frag loads conflict-free
#define GBS 136   // Bs stride (pad 8) -> frag loads conflict-free

__global__ __launch_bounds__(256)
void gemm_tf32(const float* __restrict__ A, const float* __restrict__ B,
               float* __restrict__ C, int M, int N, int K)
{
    __shared__ unsigned As[128 * GAS];
    __shared__ unsigned Bs[32 * GBS];

    const int tid  = threadIdx.x;
    const int lane = tid & 31;
    const int wid  = tid >> 5;
    const int gid  = lane >> 2;
    const int tig  = lane & 3;
    const int wm   = wid >> 2;     // 0..1
    const int wn   = wid & 3;      // 0..3
    const int bM   = blockIdx.y * 128;
    const int bN   = blockIdx.x * 128;

    float acc[4][4][4];
    #pragma unroll
    for (int mi = 0; mi < 4; mi++)
        #pragma unroll
        for (int nj = 0; nj < 4; nj++)
            #pragma unroll
            for (int e = 0; e < 4; e++) acc[mi][nj][e] = 0.0f;

    for (int kb = 0; kb < K; kb += 32) {
        // Load A tile 128x32 (4 float4 per thread)
        #pragma unroll
        for (int r = 0; r < 4; r++) {
            int idx = tid + r * 256;
            int row = idx >> 3;
            int c   = (idx & 7) * 4;
            float4 v = *(const float4*)(A + (size_t)(bM + row) * K + kb + c);
            uint4 t = make_uint4(f2tf32(v.x), f2tf32(v.y), f2tf32(v.z), f2tf32(v.w));
            *(uint4*)&As[row * GAS + c] = t;
        }
        // Load B tile 32x128
        #pragma unroll
        for (int r = 0; r < 4; r++) {
            int idx = tid + r * 256;
            int row = idx >> 5;
            int c   = (idx & 31) * 4;
            float4 v = *(const float4*)(B + (size_t)(kb + row) * N + bN + c);
            uint4 t = make_uint4(f2tf32(v.x), f2tf32(v.y), f2tf32(v.z), f2tf32(v.w));
            *(uint4*)&Bs[row * GBS + c] = t;
        }
        __syncthreads();

        #pragma unroll
        for (int ks = 0; ks < 4; ks++) {
            unsigned af[4][4], bf[4][2];
            #pragma unroll
            for (int mi = 0; mi < 4; mi++) {
                int m = wm * 64 + mi * 16 + gid;
                int k = ks * 8 + tig;
                af[mi][0] = As[m * GAS + k];
                af[mi][1] = As[(m + 8) * GAS + k];
                af[mi][2] = As[m * GAS + k + 4];
                af[mi][3] = As[(m + 8) * GAS + k + 4];
            }
            #pragma unroll
            for (int nj = 0; nj < 4; nj++) {
                int n = wn * 32 + nj * 8 + gid;
                int k = ks * 8 + tig;
                bf[nj][0] = Bs[k * GBS + n];
                bf[nj][1] = Bs[(k + 4) * GBS + n];
            }
            #pragma unroll
            for (int mi = 0; mi < 4; mi++)
                #pragma unroll
                for (int nj = 0; nj < 4; nj++)
                    mma_tf32(acc[mi][nj], af[mi], bf[nj]);
        }
        __syncthreads();
    }

    // Epilogue
    #pragma unroll
    for (int mi = 0; mi < 4; mi++) {
        #pragma unroll
        for (int nj = 0; nj < 4; nj++) {
            int row = bM + wm * 64 + mi * 16 + gid;
            int col = bN + wn * 32 + nj * 8 + 2 * tig;
            float2 lo = make_float2(acc[mi][nj][0], acc[mi][nj][1]);
            float2 hi = make_float2(acc[mi][nj][2], acc[mi][nj][3]);
            *(float2*)(C + (size_t)row * N + col) = lo;
            *(float2*)(C + (size_t)(row + 8) * N + col) = hi;
        }
    }
}

// ---------------------------------------------------------------------------
// Tensor-core flash attention (causal, tf32 mma, fp32 accum).
// CTA: 128 query rows, 4 warps x 32 rows (2 m16 tiles each). 64-key tiles.
// Online softmax in base-2 domain (scale*log2e folded into Q).
// grid: (T/128, B*H), block 128, dynamic smem 70656 B.
// ---------------------------------------------------------------------------
#define QS 68    // Q smem stride (pad 4): frag loads conflict-free
#define KSS 68   // K smem stride
#define VSS 72   // V smem stride (pad 8): B-frag loads conflict-free
#define ATT_SMEM_FLOATS (128 * QS + 64 * KSS + 64 * VSS)   // 17664
#define ATT_SMEM_BYTES  (ATT_SMEM_FLOATS * 4)              // 70656

extern __shared__ unsigned sm_att[];

__global__ __launch_bounds__(128)
void attn_tc()
{
    unsigned* Qs  = sm_att;
    unsigned* Ksm = sm_att + 128 * QS;
    unsigned* Vsm = Ksm + 64 * KSS;

    const int tid  = threadIdx.x;
    const int lane = tid & 31;
    const int w    = tid >> 5;
    const int gid  = lane >> 2;
    const int tig  = lane & 3;
    const int qt   = blockIdx.x;
    const int bh   = blockIdx.y;
    const int b    = bh >> 4;
    const int h    = bh & 15;

    const float* base = g_qkv + (size_t)b * TT * N3;
    const float qscale = 0.125f * 1.44269504f;   // 1/sqrt(64) * log2(e)

    // Load Q tile (128 x 64), scaled, tf32
    #pragma unroll
    for (int r = 0; r < 16; r++) {
        int idx = tid + r * 128;
        int row = idx >> 4;
        int c   = (idx & 15) * 4;
        float4 v = *(const float4*)(base + (size_t)(qt * 128 + row) * N3 + h * HD + c);
        uint4 t = make_uint4(f2tf32(v.x * qscale), f2tf32(v.y * qscale),
                             f2tf32(v.z * qscale), f2tf32(v.w * qscale));
        *(uint4*)&Qs[row * QS + c] = t;
    }

    float o[2][8][4];
    #pragma unroll
    for (int mi = 0; mi < 2; mi++)
        #pragma unroll
        for (int nj = 0; nj < 8; nj++)
            #pragma unroll
            for (int e = 0; e < 4; e++) o[mi][nj][e] = 0.0f;
    float mst[4] = {-1e30f, -1e30f, -1e30f, -1e30f};
    float lst[4] = {0.f, 0.f, 0.f, 0.f};

    const int ntiles = 2 * qt + 2;

    for (int kt = 0; kt < ntiles; kt++) {
        __syncthreads();   // previous iter's reads done before overwrite
        const float* kb_ = base + (size_t)(kt * 64) * N3 + CC + h * HD;
        const float* vb_ = base + (size_t)(kt * 64) * N3 + 2 * CC + h * HD;
        #pragma unroll
        for (int r = 0; r < 8; r++) {
            int idx = tid + r * 128;
            int row = idx >> 4;
            int c   = (idx & 15) * 4;
            float4 kv = *(const float4*)(kb_ + (size_t)row * N3 + c);
            float4 vv = *(const float4*)(vb_ + (size_t)row * N3 + c);
            *(uint4*)&Ksm[row * KSS + c] =
                make_uint4(f2tf32(kv.x), f2tf32(kv.y), f2tf32(kv.z), f2tf32(kv.w));
            *(uint4*)&Vsm[row * VSS + c] =
                make_uint4(f2tf32(vv.x), f2tf32(vv.y), f2tf32(vv.z), f2tf32(vv.w));
        }
        __syncthreads();

        // --- S = Q @ K^T (in log2 domain) ---
        float s[2][8][4];
        #pragma unroll
        for (int mi = 0; mi < 2; mi++)
            #pragma unroll
            for (int nj = 0; nj < 8; nj++)
                #pragma unroll
                for (int e = 0; e < 4; e++) s[mi][nj][e] = 0.0f;

        #pragma unroll
        for (int ks = 0; ks < 8; ks++) {
            unsigned a[2][4];
            #pragma unroll
            for (int mi = 0; mi < 2; mi++) {
                int m = w * 32 + mi * 16 + gid;
                int k = ks * 8 + tig;
                a[mi][0] = Qs[m * QS + k];
                a[mi][1] = Qs[(m + 8) * QS + k];
                a[mi][2] = Qs[m * QS + k + 4];
                a[mi][3] = Qs[(m + 8) * QS + k + 4];
            }
            #pragma unroll
            for (int nj = 0; nj < 8; nj++) {
                unsigned bf[2];
                int krow = nj * 8 + gid;
                bf[0] = Ksm[krow * KSS + ks * 8 + tig];
                bf[1] = Ksm[krow * KSS + ks * 8 + tig + 4];
                mma_tf32(s[0][nj], a[0], bf);
                mma_tf32(s[1][nj], a[1], bf);
            }
        }

        // --- causal mask (only the two diagonal tiles need it) ---
        if (kt >= 2 * qt) {
            int colbase = kt * 64 + 2 * tig;
            int rowbase = qt * 128 + w * 32 + gid;
            #pragma unroll
            for (int mi = 0; mi < 2; mi++)
                #pragma unroll
                for (int nj = 0; nj < 8; nj++)
                    #pragma unroll
                    for (int e = 0; e < 4; e++) {
                        int row = rowbase + mi * 16 + ((e >> 1) << 3);
                        int col = colbase + nj * 8 + (e & 1);
                        if (col > row) s[mi][nj][e] = -1e30f;
                    }
        }

        // --- online softmax update (base-2) ---
        #pragma unroll
        for (int st = 0; st < 4; st++) {
            const int mi = st >> 1, hf = st & 1;
            float rm = -1e30f;
            #pragma unroll
            for (int nj = 0; nj < 8; nj++) {
                rm = fmaxf(rm, s[mi][nj][hf * 2]);
                rm = fmaxf(rm, s[mi][nj][hf * 2 + 1]);
            }
            rm = fmaxf(rm, __shfl_xor_sync(0xffffffff, rm, 1));
            rm = fmaxf(rm, __shfl_xor_sync(0xffffffff, rm, 2));
            float mnew = fmaxf(mst[st], rm);
            float alpha = ex2f(mst[st] - mnew);
            mst[st] = mnew;
            lst[st] *= alpha;
            #pragma unroll
            for (int nj = 0; nj < 8; nj++) {
                o[mi][nj][hf * 2]     *= alpha;
                o[mi][nj][hf * 2 + 1] *= alpha;
            }
            float psum = 0.0f;
            #pragma unroll
            for (int nj = 0; nj < 8; nj++) {
                float p0 = ex2f(s[mi][nj][hf * 2]     - mnew);
                float p1 = ex2f(s[mi][nj][hf * 2 + 1] - mnew);
                s[mi][nj][hf * 2]     = p0;
                s[mi][nj][hf * 2 + 1] = p1;
                psum += p0 + p1;
            }
            psum += __shfl_xor_sync(0xffffffff, psum, 1);
            psum += __shfl_xor_sync(0xffffffff, psum, 2);
            lst[st] += psum;
        }

        // --- O += P @ V ---
        const int src0 = (lane & ~3) | (tig >> 1);
        const int src1 = src0 + 2;
        const bool odd = tig & 1;
        #pragma unroll
        for (int kc = 0; kc < 8; kc++) {
            unsigned pa[2][4];
            #pragma unroll
            for (int mi = 0; mi < 2; mi++) {
                float c0 = s[mi][kc][0], c1 = s[mi][kc][1];
                float c2 = s[mi][kc][2], c3 = s[mi][kc][3];
                float v00 = __shfl_sync(0xffffffff, c0, src0);
                float v01 = __shfl_sync(0xffffffff, c1, src0);
                float v10 = __shfl_sync(0xffffffff, c0, src1);
                float v11 = __shfl_sync(0xffffffff, c1, src1);
                float v20 = __shfl_sync(0xffffffff, c2, src0);
                float v21 = __shfl_sync(0xffffffff, c3, src0);
                float v30 = __shfl_sync(0xffffffff, c2, src1);
                float v31 = __shfl_sync(0xffffffff, c3, src1);
                pa[mi][0] = __float_as_uint(odd ? v01 : v00);
                pa[mi][2] = __float_as_uint(odd ? v11 : v10);
                pa[mi][1] = __float_as_uint(odd ? v21 : v20);
                pa[mi][3] = __float_as_uint(odd ? v31 : v30);
            }
            #pragma unroll
            for (int hj = 0; hj < 8; hj++) {
                unsigned bf[2];
                bf[0] = Vsm[(kc * 8 + tig) * VSS + hj * 8 + gid];
                bf[1] = Vsm[(kc * 8 + tig + 4) * VSS + hj * 8 + gid];
                mma_tf32(o[0][hj], pa[0], bf);
                mma_tf32(o[1][hj], pa[1], bf);
            }
        }
    }

    // --- normalize + write [B,T,C] ---
    #pragma unroll
    for (int mi = 0; mi < 2; mi++) {
        float inv0 = 1.0f / lst[2 * mi];
        float inv1 = 1.0f / lst[2 * mi + 1];
        #pragma unroll
        for (int nj = 0; nj < 8; nj++) {
            int row = qt * 128 + w * 32 + mi * 16 + gid;
            int col = nj * 8 + 2 * tig;
            float* op = g_attn + (size_t)(b * TT + row) * CC + h * HD + col;
            *(float2*)op = make_float2(o[mi][nj][0] * inv0, o[mi][nj][1] * inv0);
            *(float2*)(op + (size_t)8 * CC) =
                make_float2(o[mi][nj][2] * inv1, o[mi][nj][3] * inv1);
        }
    }
}

// ---------------------------------------------------------------------------
// Launch
// ---------------------------------------------------------------------------
extern "C" void kernel_launch(void* const* d_in, const int* in_sizes, int n_in,
                              void* d_out, int out_size)
{
    const float* x     = (const float*)d_in[0];   // [B,T,C]
    const float* w_qkv = (const float*)d_in[1];   // [C,3C]
    const float* w_out = (const float*)d_in[2];   // [C,C]
    float* out = (float*)d_out;                   // [B,T,C]

    float* qkv_ptr = nullptr;
    float* attn_ptr = nullptr;
    cudaGetSymbolAddress((void**)&qkv_ptr, g_qkv);
    cudaGetSymbolAddress((void**)&attn_ptr, g_attn);

    cudaFuncSetAttribute(attn_tc, cudaFuncAttributeMaxDynamicSharedMemorySize,
                         ATT_SMEM_BYTES);

    // 1) QKV projection: [8192,1024] @ [1024,3072]
    {
        dim3 grid(N3 / 128, M_ROWS / 128);
        gemm_tf32<<<grid, 256>>>(x, w_qkv, qkv_ptr, M_ROWS, N3, CC);
    }
    // 2) Flash attention (tensor cores)
    {
        dim3 grid(TT / 128, BB * HH);
        attn_tc<<<grid, 128, ATT_SMEM_BYTES>>>();
    }
    // 3) Output projection: [8192,1024] @ [1024,1024]
    {
        dim3 grid(CC / 128, M_ROWS / 128);
        gemm_tf32<<<grid, 256>>>(attn_ptr, w_out, out, M_ROWS, CC, CC);
    }
}